// round 13
// baseline (speedup 1.0000x reference)
#include <cuda_runtime.h>

// EfficientGCN preprocess on GB300 — v7 structure + cheap acos/div math.
// x: (N=128, C=3, T=300, V=25, M=2) fp32, conn: int32[25]
// out: (N, 3, 6, T, V, M) fp32
//
// Block = one (n, 20-row t-tile), 3ch x 22rows x 50 floats staged (13.2KB).
// 250 threads each own one float4 = 2 adjacent joints of a 2-row segment.
// Self & t+2 reads are single LDS.128; t+1 is 2x LDS.64; center/parent scalar.
// 18 STG.128 streaming stores. acos via A&S 4.4.46 minimax (abs err <= 2e-8),
// reciprocal lengths via __fdividef (MUFU.RCP) — both well inside 1e-3 tol.

#define N_ 128
#define C_ 3
#define T_ 300
#define V_ 25
#define RPT 20            // t-rows computed per tile
#define TILE_ROWS 22      // RPT + 2 halo
#define TILES_PER_N 15    // 300 / 20
#define ROWF 50           // floats per t-row (V*M)
#define CSLAB 15000       // floats per channel slab (T*ROWF)
#define SM_CH 1100        // floats per channel in smem (TILE_ROWS*ROWF)

__device__ __forceinline__ float acos_fast(float x)
{
    // Abramowitz & Stegun 4.4.46: acos(a) = sqrt(1-a)*p7(a), a in [0,1], |err|<=2e-8
    float ax = fabsf(x);
    float p = -0.0012624911f;
    p = fmaf(p, ax,  0.0066700901f);
    p = fmaf(p, ax, -0.0170881256f);
    p = fmaf(p, ax,  0.0308918810f);
    p = fmaf(p, ax, -0.0501743046f);
    p = fmaf(p, ax,  0.0889789874f);
    p = fmaf(p, ax, -0.2145988016f);
    p = fmaf(p, ax,  1.5707963050f);
    float r = sqrtf(1.0f - ax) * p;
    return (x >= 0.0f) ? r : (3.14159265358979f - r);
}

__global__ __launch_bounds__(256, 6) void egcn_preprocess_v8(
    const float* __restrict__ x,
    const int* __restrict__ conn,
    float* __restrict__ out)
{
    __shared__ float sm[C_ * SM_CH];          // 3300 floats = 13.2 KB

    const int tid  = threadIdx.x;
    const int n    = blockIdx.x / TILES_PER_N;
    const int tile = blockIdx.x % TILES_PER_N;
    const int t0   = tile * RPT;

    const float* xn = x + n * (C_ * CSLAB);

    // ---- stage tile: 3 x 1100 floats = 825 float4 ----
    if (t0 + TILE_ROWS <= T_) {
        #pragma unroll
        for (int k = 0; k < 4; ++k) {
            int idx = tid + k * 256;
            if (idx < 825) {
                int c   = idx / 275;
                int rem = idx - c * 275;
                const float4* src = (const float4*)(xn + c * CSLAB + t0 * ROWF);
                ((float4*)(sm + c * SM_CH))[rem] = src[rem];
            }
        }
    } else {
        // last tile (t0=280): clamp halo rows 300,301 -> 299
        for (int idx = tid; idx < C_ * TILE_ROWS * V_; idx += 256) {
            int c   = idx / (TILE_ROWS * V_);
            int rem = idx - c * (TILE_ROWS * V_);
            int r   = rem / V_;
            int v   = rem - r * V_;
            int gt  = t0 + r; if (gt > T_ - 1) gt = T_ - 1;
            ((float2*)(sm + c * SM_CH + r * ROWF))[v] =
                ((const float2*)(xn + c * CSLAB + gt * ROWF))[v];
        }
    }
    __syncthreads();

    if (tid >= 250) return;

    const int rp = tid / 25;                  // row-pair 0..9
    const int k  = tid - rp * 25;             // float4 column 0..24

    // joints jA=2k, jB=2k+1 within the 100-float (2-row) segment
    const int rA = 2 * rp + (k >= 13);
    const int rB = 2 * rp + (k >= 12);
    const int vA = 2 * k     - V_ * (k >= 13);
    const int vB = 2 * k + 1 - V_ * (k >= 12);

    const int pvA = __ldg(&conn[vA]);
    const int pvB = __ldg(&conn[vB]);
    const float selA = (t0 + rA < T_ - 2) ? 1.0f : 0.0f;
    const float selB = (t0 + rB < T_ - 2) ? 1.0f : 0.0f;
    const float4 sel4 = make_float4(selA, selA, selB, selB);

    const int seg = 100 * rp + 4 * k;         // packed float4 offset in channel

    float* ob = out + (size_t)n * 18 * CSLAB + (t0 + 2 * rp) * ROWF + 4 * k;

    float4 b[3];                              // bone vecs, live across channels

#pragma unroll
    for (int c = 0; c < C_; ++c) {
        const float* base = sm + c * SM_CH;

        float4 a    = *(const float4*)(base + seg);                // self (aligned)
        float4 n2   = *(const float4*)(base + seg + 2 * ROWF);     // t+2 (aligned)
        float2 n1lo = *(const float2*)(base + seg + ROWF);         // t+1 (8B aligned)
        float2 n1hi = *(const float2*)(base + seg + ROWF + 2);

        float2 cA = ((const float2*)(base + rA * ROWF))[1];
        float2 cB = ((const float2*)(base + rB * ROWF))[1];
        float2 pA = ((const float2*)(base + rA * ROWF))[pvA];
        float2 pB = ((const float2*)(base + rB * ROWF))[pvB];

        __stcs((float4*)(ob + c * CSLAB), a);                                    // joint: x
        __stcs((float4*)(ob + (c + 3) * CSLAB),
               make_float4(a.x - cA.x, a.y - cA.y, a.z - cB.x, a.w - cB.y));     // x - center
        __stcs((float4*)(ob + (c + 6) * CSLAB),
               make_float4((n1lo.x - a.x) * sel4.x, (n1lo.y - a.y) * sel4.y,
                           (n1hi.x - a.z) * sel4.z, (n1hi.y - a.w) * sel4.w));   // v1
        __stcs((float4*)(ob + (c + 9) * CSLAB),
               make_float4((n2.x - a.x) * sel4.x, (n2.y - a.y) * sel4.y,
                           (n2.z - a.z) * sel4.z, (n2.w - a.w) * sel4.w));       // v2

        b[c] = make_float4(a.x - pA.x, a.y - pA.y, a.z - pB.x, a.w - pB.y);
        __stcs((float4*)(ob + (c + 12) * CSLAB), b[c]);                          // bone vec
    }

    // ---- bone angles ----
    float4 s = make_float4(
        b[0].x * b[0].x + b[1].x * b[1].x + b[2].x * b[2].x,
        b[0].y * b[0].y + b[1].y * b[1].y + b[2].y * b[2].y,
        b[0].z * b[0].z + b[1].z * b[1].z + b[2].z * b[2].z,
        b[0].w * b[0].w + b[1].w * b[1].w + b[2].w * b[2].w);
    float4 r = make_float4(__fdividef(1.0f, sqrtf(s.x) + 1e-4f),
                           __fdividef(1.0f, sqrtf(s.y) + 1e-4f),
                           __fdividef(1.0f, sqrtf(s.z) + 1e-4f),
                           __fdividef(1.0f, sqrtf(s.w) + 1e-4f));

#pragma unroll
    for (int c = 0; c < C_; ++c) {
        __stcs((float4*)(ob + (c + 15) * CSLAB),
               make_float4(acos_fast(b[c].x * r.x), acos_fast(b[c].y * r.y),
                           acos_fast(b[c].z * r.z), acos_fast(b[c].w * r.w)));   // bone angle
    }
}

extern "C" void kernel_launch(void* const* d_in, const int* in_sizes, int n_in,
                              void* d_out, int out_size)
{
    const float* x  = (const float*)d_in[0];
    const int* conn = (const int*)d_in[1];
    float* out      = (float*)d_out;

    const int blocks = N_ * TILES_PER_N;     // 1920
    egcn_preprocess_v8<<<blocks, 256>>>(x, conn, out);
}

// round 14
// speedup vs baseline: 1.0012x; 1.0012x over previous
#include <cuda_runtime.h>

// EfficientGCN preprocess on GB300 — pure-gmem float4-paired version.
// x: (N=128, C=3, T=300, V=25, M=2) fp32, conn: int32[25]
// out: (N, 3, 6, T, V, M) fp32
//
// One thread per (n, row-pair, float4-column): 480K threads, each owning one
// 16B-aligned float4 (= 2 adjacent joints, straddle handled by uniform index
// math) across all 18 output slabs. No smem, no syncthreads.
//   self / t+2 : LDG.128 (aligned, warp-contiguous -> perfectly coalesced)
//   t+1        : 2x LDG.64 (row offset 50 floats -> 8B aligned)
//   center     : 2x LDG.64 broadcast (L1 hit)
//   parent     : 2x LDG.64 small gather within the 2 rows (L1 hit)
// Stores: 18x STG.128 streaming (__stcs), warp-contiguous.
// acos via A&S 4.4.46 minimax, reciprocal via __fdividef.

#define N_ 128
#define C_ 3
#define T_ 300
#define V_ 25
#define ROWF 50           // floats per t-row (V*M)
#define CSLAB 15000       // floats per channel slab (T*ROWF)
#define RPAIRS 150        // row-pairs per sequence (T/2)

__device__ __forceinline__ float acos_fast(float x)
{
    float ax = fabsf(x);
    float p = -0.0012624911f;
    p = fmaf(p, ax,  0.0066700901f);
    p = fmaf(p, ax, -0.0170881256f);
    p = fmaf(p, ax,  0.0308918810f);
    p = fmaf(p, ax, -0.0501743046f);
    p = fmaf(p, ax,  0.0889789874f);
    p = fmaf(p, ax, -0.2145988016f);
    p = fmaf(p, ax,  1.5707963050f);
    float r = sqrtf(1.0f - ax) * p;
    return (x >= 0.0f) ? r : (3.14159265358979f - r);
}

__global__ __launch_bounds__(256, 6) void egcn_preprocess_v9(
    const float* __restrict__ x,
    const int* __restrict__ conn,
    float* __restrict__ out)
{
    const int P = N_ * RPAIRS * 25;          // 480000
    int q = blockIdx.x * blockDim.x + threadIdx.x;
    if (q >= P) return;

    const int k   = q % 25;                  // float4 column 0..24
    const int nrp = q / 25;
    const int rp  = nrp % RPAIRS;            // row-pair 0..149
    const int n   = nrp / RPAIRS;

    // joints jA=2k, jB=2k+1 within the 100-float (2-row) segment
    const int dA = (k >= 13);
    const int dB = (k >= 12);
    const int rA = 2 * rp + dA;              // global t of joint A
    const int rB = 2 * rp + dB;
    const int vA = 2 * k     - V_ * dA;
    const int vB = 2 * k + 1 - V_ * dB;

    const int pvA = __ldg(&conn[vA]);
    const int pvB = __ldg(&conn[vB]);
    const float selA = (rA < T_ - 2) ? 1.0f : 0.0f;
    const float selB = (rB < T_ - 2) ? 1.0f : 0.0f;

    const int seg = 100 * rp + 4 * k;        // packed float4 offset in channel slab

    const float* xn = x + n * (C_ * CSLAB);
    float* ob = out + (size_t)n * 18 * CSLAB + seg;

    float4 b[3];                             // bone vecs, live across channels

#pragma unroll
    for (int c = 0; c < C_; ++c) {
        const float* base = xn + c * CSLAB;

        float4 a    = *(const float4*)(base + seg);                // self (aligned)
        // t+1 / t+2 rows: clamp so loads stay in-bounds at the sequence end;
        // results are zeroed by sel when out of range.
        const int o1 = (2 * rp + 2 < T_) ? ROWF     : 0;
        const int o2 = (2 * rp + 2 < T_) ? 2 * ROWF : 0;
        float2 n1lo = *(const float2*)(base + seg + o1);
        float2 n1hi = *(const float2*)(base + seg + o1 + 2);
        float4 n2   = *(const float4*)(base + seg + o2);

        float2 cA = ((const float2*)(base + rA * ROWF))[1];
        float2 cB = ((const float2*)(base + rB * ROWF))[1];
        float2 pA = ((const float2*)(base + rA * ROWF))[pvA];
        float2 pB = ((const float2*)(base + rB * ROWF))[pvB];

        __stcs((float4*)(ob + c * CSLAB), a);                                    // joint: x
        __stcs((float4*)(ob + (c + 3) * CSLAB),
               make_float4(a.x - cA.x, a.y - cA.y, a.z - cB.x, a.w - cB.y));     // x - center
        __stcs((float4*)(ob + (c + 6) * CSLAB),
               make_float4((n1lo.x - a.x) * selA, (n1lo.y - a.y) * selA,
                           (n1hi.x - a.z) * selB, (n1hi.y - a.w) * selB));       // v1
        __stcs((float4*)(ob + (c + 9) * CSLAB),
               make_float4((n2.x - a.x) * selA, (n2.y - a.y) * selA,
                           (n2.z - a.z) * selB, (n2.w - a.w) * selB));           // v2

        b[c] = make_float4(a.x - pA.x, a.y - pA.y, a.z - pB.x, a.w - pB.y);
        __stcs((float4*)(ob + (c + 12) * CSLAB), b[c]);                          // bone vec
    }

    // ---- bone angles ----
    float4 s = make_float4(
        b[0].x * b[0].x + b[1].x * b[1].x + b[2].x * b[2].x,
        b[0].y * b[0].y + b[1].y * b[1].y + b[2].y * b[2].y,
        b[0].z * b[0].z + b[1].z * b[1].z + b[2].z * b[2].z,
        b[0].w * b[0].w + b[1].w * b[1].w + b[2].w * b[2].w);
    float4 r = make_float4(__fdividef(1.0f, sqrtf(s.x) + 1e-4f),
                           __fdividef(1.0f, sqrtf(s.y) + 1e-4f),
                           __fdividef(1.0f, sqrtf(s.z) + 1e-4f),
                           __fdividef(1.0f, sqrtf(s.w) + 1e-4f));

#pragma unroll
    for (int c = 0; c < C_; ++c) {
        __stcs((float4*)(ob + (c + 15) * CSLAB),
               make_float4(acos_fast(b[c].x * r.x), acos_fast(b[c].y * r.y),
                           acos_fast(b[c].z * r.z), acos_fast(b[c].w * r.w)));   // bone angle
    }
}

extern "C" void kernel_launch(void* const* d_in, const int* in_sizes, int n_in,
                              void* d_out, int out_size)
{
    const float* x  = (const float*)d_in[0];
    const int* conn = (const int*)d_in[1];
    float* out      = (float*)d_out;

    const int P = N_ * RPAIRS * 25;          // 480000
    const int threads = 256;
    const int blocks = (P + threads - 1) / threads;   // 1875
    egcn_preprocess_v9<<<blocks, threads>>>(x, conn, out);
}